// round 16
// baseline (speedup 1.0000x reference)
#include <cuda_runtime.h>
#include <cuda_fp16.h>
#include <math.h>
#include <stdint.h>

// Problem shape (fixed)
#define BB 4
#define TT 2048
#define CC 1024
#define HH 16
#define HD 64
#define MM (BB * TT)     // 8192 rows
#define C3 (3 * CC)      // 3072

// Scratch (device globals — allocation-free per harness rules)
__device__ float g_qkv[(size_t)MM * C3];   // fp16 qkv (48MB) + fp16 vT (32MB)
__device__ float g_y[(size_t)MM * CC];     // fp16 ybuf
__device__ float g_xt[(size_t)MM * CC];    // fp16 x
__device__ float g_wt[(size_t)C3 * CC + (size_t)CC * CC];  // fp16 W^T

// ---------------------------------------------------------------------------
// PTX helpers (baseline features only: harness PTX target is compute_103,
// which rejects tcgen05/accelerated-arch instructions).
// ---------------------------------------------------------------------------
#define CP_ASYNC16(dst, src) \
    asm volatile("cp.async.cg.shared.global [%0], [%1], 16;\n" \
                 :: "r"(dst), "l"(src) : "memory")
#define CP_COMMIT()  asm volatile("cp.async.commit_group;\n" ::: "memory")
#define CP_WAIT1()   asm volatile("cp.async.wait_group 1;\n" ::: "memory")

__device__ __forceinline__ uint32_t smem_u32(const void* p) {
    uint32_t a;
    asm("{ .reg .u64 t; cvta.to.shared.u64 t, %1; cvt.u32.u64 %0, t; }"
        : "=r"(a) : "l"(p));
    return a;
}

__device__ __forceinline__ void ldsm4(uint32_t r[4], uint32_t addr) {
    asm volatile("ldmatrix.sync.aligned.m8n8.x4.shared.b16 {%0,%1,%2,%3}, [%4];"
                 : "=r"(r[0]), "=r"(r[1]), "=r"(r[2]), "=r"(r[3]) : "r"(addr));
}

__device__ __forceinline__ void mma_f16(float c[4], const uint32_t a[4],
                                        uint32_t b0, uint32_t b1) {
    asm volatile(
        "mma.sync.aligned.m16n8k16.row.col.f32.f16.f16.f32 "
        "{%0,%1,%2,%3}, {%4,%5,%6,%7}, {%8,%9}, {%0,%1,%2,%3};"
        : "+f"(c[0]), "+f"(c[1]), "+f"(c[2]), "+f"(c[3])
        : "r"(a[0]), "r"(a[1]), "r"(a[2]), "r"(a[3]), "r"(b0), "r"(b1));
}

// ---------------------------------------------------------------------------
// Conversion passes.
// ---------------------------------------------------------------------------
__global__ __launch_bounds__(256)
void conv_f16(const float* __restrict__ in, __half* __restrict__ out, int n8)
{
    int i = blockIdx.x * 256 + threadIdx.x;
    if (i < n8) {
        float4 a = ((const float4*)in)[i * 2];
        float4 b = ((const float4*)in)[i * 2 + 1];
        __half2 h[4];
        h[0] = __floats2half2_rn(a.x, a.y);
        h[1] = __floats2half2_rn(a.z, a.w);
        h[2] = __floats2half2_rn(b.x, b.y);
        h[3] = __floats2half2_rn(b.z, b.w);
        ((float4*)out)[i] = *(float4*)h;
    }
}

__global__ __launch_bounds__(256)
void transpose_f16(const float* __restrict__ in, __half* __restrict__ out,
                   int R, int Cc)
{
    __shared__ float t[32][33];
    int c0 = blockIdx.x * 32, r0 = blockIdx.y * 32;
    int x = threadIdx.x, y = threadIdx.y;
    #pragma unroll
    for (int i = 0; i < 32; i += 8)
        t[y + i][x] = in[(size_t)(r0 + y + i) * Cc + c0 + x];
    __syncthreads();
    #pragma unroll
    for (int i = 0; i < 32; i += 8)
        out[(size_t)(c0 + y + i) * R + r0 + x] = __float2half(t[x][y + i]);
}

// ---------------------------------------------------------------------------
// FP16 mma.sync GEMM with ldmatrix fragment loads.
// CTA 128x128x64, 256 threads (8 warps: 2M x 4N), warp tile 64x32.
// V_FUSE: columns >= 2C scattered directly into vT[b,h,d,t].
// ---------------------------------------------------------------------------
#define BM 128
#define BN 128
#define BKH 64
#define HSTR 72
#define NSTAGE 3
#define TILE_H (128 * HSTR)

template<bool OUT_F16, bool V_FUSE>
__global__ __launch_bounds__(256, 2)
void gemm_f16mma(const __half* __restrict__ A, const __half* __restrict__ BT,
                 const float* __restrict__ bias, void* __restrict__ Cout,
                 __half* __restrict__ vTout,
                 int M, int N, int K)
{
    extern __shared__ __align__(16) __half smh[];
    __half* Asm = smh;
    __half* Bsm = smh + NSTAGE * TILE_H;

    const int tid  = threadIdx.x;
    const int wid  = tid >> 5;
    const int lane = tid & 31;
    const int quad = lane >> 2;
    const int tq   = lane & 3;
    const int warpM = wid & 1;
    const int warpN = wid >> 1;
    const int row0 = blockIdx.y * BM;
    const int col0 = blockIdx.x * BN;

    const int aRowOff = (lane & 7) + ((lane >> 3) & 1) * 8;
    const int aKOff   = (lane >> 4) * 8;
    const int bRowOff = ((lane >> 4) * 8) + (lane & 7);
    const int bKOff   = ((lane >> 3) & 1) * 8;

    // Hoist bias (8 values per thread, loop-invariant).
    float bx[4][2];
    #pragma unroll
    for (int nt = 0; nt < 4; nt++) {
        const int col = col0 + warpN * 32 + nt * 8 + 2 * tq;
        bx[nt][0] = __ldg(bias + col);
        bx[nt][1] = __ldg(bias + col + 1);
    }

    float acc[4][4][4];
    #pragma unroll
    for (int mt = 0; mt < 4; mt++)
        #pragma unroll
        for (int nt = 0; nt < 4; nt++)
            #pragma unroll
            for (int j = 0; j < 4; j++) acc[mt][nt][j] = 0.0f;

    const uint32_t sAu = smem_u32(Asm);
    const uint32_t sBu = smem_u32(Bsm);

    auto load_tile = [&](int kt) {
        const int s = kt % NSTAGE;
        const int k0 = kt * BKH;
        #pragma unroll
        for (int i = 0; i < 4; i++) {
            const int id  = tid + i * 256;
            const int r   = id >> 3;
            const int kc  = (id & 7) << 3;
            CP_ASYNC16(sAu + (uint32_t)(s * TILE_H + r * HSTR + kc) * 2,
                       A + (size_t)(row0 + r) * K + k0 + kc);
            CP_ASYNC16(sBu + (uint32_t)(s * TILE_H + r * HSTR + kc) * 2,
                       BT + (size_t)(col0 + r) * K + k0 + kc);
        }
        CP_COMMIT();
    };

    const int NKT = K / BKH;   // 16
    load_tile(0);
    load_tile(1);

    for (int kt = 0; kt < NKT; kt++) {
        CP_WAIT1();
        __syncthreads();
        if (kt + 2 < NKT) load_tile(kt + 2);

        const uint32_t aBase = sAu + (uint32_t)((kt % NSTAGE) * TILE_H) * 2;
        const uint32_t bBase = sBu + (uint32_t)((kt % NSTAGE) * TILE_H) * 2;

        #pragma unroll
        for (int ks = 0; ks < 4; ks++) {
            uint32_t af[4][4];
            #pragma unroll
            for (int mt = 0; mt < 4; mt++) {
                const int row = warpM * 64 + mt * 16 + aRowOff;
                const int kh  = ks * 16 + aKOff;
                ldsm4(af[mt], aBase + (uint32_t)(row * HSTR + kh) * 2);
            }
            uint32_t bf[2][4];
            #pragma unroll
            for (int ntp = 0; ntp < 2; ntp++) {
                const int row = warpN * 32 + ntp * 16 + bRowOff;
                const int kh  = ks * 16 + bKOff;
                ldsm4(bf[ntp], bBase + (uint32_t)(row * HSTR + kh) * 2);
            }
            #pragma unroll
            for (int nt = 0; nt < 4; nt++) {
                uint32_t b0 = bf[nt >> 1][(nt & 1) * 2];
                uint32_t b1 = bf[nt >> 1][(nt & 1) * 2 + 1];
                #pragma unroll
                for (int mt = 0; mt < 4; mt++)
                    mma_f16(acc[mt][nt], af[mt], b0, b1);
            }
        }
    }

    const bool vblock = V_FUSE && (col0 >= 2 * CC);
    #pragma unroll
    for (int mt = 0; mt < 4; mt++) {
        #pragma unroll
        for (int half = 0; half < 2; half++) {
            const int row = row0 + warpM * 64 + mt * 16 + quad + half * 8;
            #pragma unroll
            for (int nt = 0; nt < 4; nt++) {
                const int col = col0 + warpN * 32 + nt * 8 + 2 * tq;
                float vx = acc[mt][nt][half * 2 + 0] + bx[nt][0];
                float vy = acc[mt][nt][half * 2 + 1] + bx[nt][1];
                if (OUT_F16) {
                    if (vblock) {
                        const int cc = col - 2 * CC;
                        const int hh = cc >> 6, dd = cc & 63;
                        const int bb = row >> 11, tt = row & 2047;
                        __half* dst = vTout + ((size_t)(bb * HH + hh) * HD) * TT;
                        dst[(size_t)dd * TT + tt]       = __float2half(vx);
                        dst[(size_t)(dd + 1) * TT + tt] = __float2half(vy);
                    } else {
                        __half* crow = (__half*)Cout + (size_t)row * N;
                        *(__half2*)(crow + col) = __floats2half2_rn(vx, vy);
                    }
                } else {
                    float* crow = (float*)Cout + (size_t)row * N;
                    float2 v; v.x = vx; v.y = vy;
                    *(float2*)(crow + col) = v;
                }
            }
        }
    }
}

// ---------------------------------------------------------------------------
// Flash attention, FP16 mma + ldmatrix. BQ=128, 128 threads (4 warps).
// Base-2 softmax; exp via ex2.approx.f16x2 (h2exp2) — the fp16 result IS the
// PV mma operand, and li is summed from those same quantized values.
// Q/K from fp16 qkv; V from vT [d][t]. Q frags hoisted; P aliases Q staging;
// K/V cp.async double-buffered.
// ---------------------------------------------------------------------------
#define BQ 128
#define HS2 72
#define KV_H (64 * HS2)

__global__ __launch_bounds__(128, 2)
void flash_attn_f16(const __half* __restrict__ qkvh,
                    const __half* __restrict__ vT,
                    __half* __restrict__ y)
{
    extern __shared__ __align__(16) __half smh[];
    __half* Qs  = smh;
    __half* Ps  = smh;
    __half* Kst = smh + 128 * HS2;
    __half* Vst = Kst + 2 * KV_H;

    const int tid  = threadIdx.x;
    const int w    = tid >> 5;
    const int lane = tid & 31;
    const int quad = lane >> 2;
    const int tq   = lane & 3;

    const int aRowOff = (lane & 7) + ((lane >> 3) & 1) * 8;
    const int aKOff   = (lane >> 4) * 8;
    const int bRowOff = ((lane >> 4) * 8) + (lane & 7);
    const int bKOff   = ((lane >> 3) & 1) * 8;

    const int b = blockIdx.z, h = blockIdx.y;
    const int q0 = (gridDim.x - 1 - blockIdx.x) * BQ;

    const __half* Qg = qkvh + (size_t)b * TT * C3 + h * HD;
    const __half* Kg = Qg + CC;
    const __half* Vg = vT + ((size_t)(b * HH + h) * HD) * TT;

    const uint32_t sQu = smem_u32(Qs);
    const uint32_t sKu = smem_u32(Kst);
    const uint32_t sVu = smem_u32(Vst);

    #pragma unroll
    for (int it = 0; it < 8; it++) {
        int idx = tid + it * 128;
        int r  = idx >> 3;
        int hc = (idx & 7) << 3;
        CP_ASYNC16(sQu + (uint32_t)(r * HS2 + hc) * 2,
                   Qg + (size_t)(q0 + r) * C3 + hc);
    }
    CP_COMMIT();

    auto load_kv = [&](int jt) {
        const int s = jt & 1;
        const int k0 = jt << 6;
        #pragma unroll
        for (int it = 0; it < 4; it++) {
            int idx = tid + it * 128;
            int r  = idx >> 3;
            int hc = (idx & 7) << 3;
            const uint32_t off = (uint32_t)(s * KV_H + r * HS2 + hc) * 2;
            CP_ASYNC16(sKu + off, Kg + (size_t)(k0 + r) * C3 + hc);
            CP_ASYNC16(sVu + off, Vg + (size_t)r * TT + k0 + hc);
        }
        CP_COMMIT();
    };

    load_kv(0);
    CP_WAIT1();
    __syncthreads();

    uint32_t qf[4][2][4];
    #pragma unroll
    for (int kc = 0; kc < 4; kc++)
        #pragma unroll
        for (int mt = 0; mt < 2; mt++) {
            const int row = w * 32 + mt * 16 + aRowOff;
            const int kh  = kc * 16 + aKOff;
            ldsm4(qf[kc][mt], sQu + (uint32_t)(row * HS2 + kh) * 2);
        }

    float mi[2][2], li[2][2];
    #pragma unroll
    for (int mt = 0; mt < 2; mt++) {
        mi[mt][0] = -1e30f; mi[mt][1] = -1e30f;
        li[mt][0] = 0.0f;   li[mt][1] = 0.0f;
    }
    float oacc[2][8][4];
    #pragma unroll
    for (int mt = 0; mt < 2; mt++)
        #pragma unroll
        for (int nt = 0; nt < 8; nt++)
            #pragma unroll
            for (int j = 0; j < 4; j++) oacc[mt][nt][j] = 0.0f;

    const int ntile = (q0 >> 6) + 2;
    for (int jt = 0; jt < ntile; jt++) {
        const int k0 = jt << 6;
        __syncthreads();
        if (jt + 1 < ntile) load_kv(jt + 1);
        CP_WAIT1();
        __syncthreads();

        if (jt == ntile - 1 && w < 2) continue;

        const bool diag = (w < 2) ? (jt == ntile - 2) : (jt == ntile - 1);
        const uint32_t kBase = sKu + (uint32_t)((jt & 1) * KV_H) * 2;
        const uint32_t vBase = sVu + (uint32_t)((jt & 1) * KV_H) * 2;

        // ---- S = Q K^T ----
        float sacc[2][8][4];
        #pragma unroll
        for (int mt = 0; mt < 2; mt++)
            #pragma unroll
            for (int nt = 0; nt < 8; nt++)
                #pragma unroll
                for (int j = 0; j < 4; j++) sacc[mt][nt][j] = 0.0f;

        #pragma unroll
        for (int kc = 0; kc < 4; kc++) {
            #pragma unroll
            for (int ntp = 0; ntp < 4; ntp++) {
                uint32_t kf[4];
                const int row = ntp * 16 + bRowOff;
                const int kh  = kc * 16 + bKOff;
                ldsm4(kf, kBase + (uint32_t)(row * HS2 + kh) * 2);
                mma_f16(sacc[0][ntp * 2],     qf[kc][0], kf[0], kf[1]);
                mma_f16(sacc[1][ntp * 2],     qf[kc][1], kf[0], kf[1]);
                mma_f16(sacc[0][ntp * 2 + 1], qf[kc][0], kf[2], kf[3]);
                mma_f16(sacc[1][ntp * 2 + 1], qf[kc][1], kf[2], kf[3]);
            }
        }

        // ---- scale (log2 domain) + causal mask ----
        const float scl2 = 0.18033688011f;   // (1/8) * log2(e)
        #pragma unroll
        for (int mt = 0; mt < 2; mt++) {
            #pragma unroll
            for (int nt = 0; nt < 8; nt++) {
                #pragma unroll
                for (int j = 0; j < 4; j++) {
                    float v = sacc[mt][nt][j] * scl2;
                    if (diag) {
                        int c = k0 + nt * 8 + 2 * tq + (j & 1);
                        int r = q0 + w * 32 + mt * 16 + quad + (j >> 1) * 8;
                        if (c > r) v = -1e30f;
                    }
                    sacc[mt][nt][j] = v;
                }
            }
        }

        // ---- online softmax (base-2, exp in f16x2; P staged in the same pass) ----
        #pragma unroll
        for (int mt = 0; mt < 2; mt++) {
            float mx0 = -1e30f, mx1 = -1e30f;
            #pragma unroll
            for (int nt = 0; nt < 8; nt++) {
                mx0 = fmaxf(mx0, fmaxf(sacc[mt][nt][0], sacc[mt][nt][1]));
                mx1 = fmaxf(mx1, fmaxf(sacc[mt][nt][2], sacc[mt][nt][3]));
            }
            mx0 = fmaxf(mx0, __shfl_xor_sync(0xffffffffu, mx0, 1));
            mx0 = fmaxf(mx0, __shfl_xor_sync(0xffffffffu, mx0, 2));
            mx1 = fmaxf(mx1, __shfl_xor_sync(0xffffffffu, mx1, 1));
            mx1 = fmaxf(mx1, __shfl_xor_sync(0xffffffffu, mx1, 2));

            float mn0 = fmaxf(mi[mt][0], mx0), mn1 = fmaxf(mi[mt][1], mx1);
            float al0 = exp2f(mi[mt][0] - mn0), al1 = exp2f(mi[mt][1] - mn1);

            const int rowA = w * 32 + mt * 16 + quad;
            float sum0 = 0.0f, sum1 = 0.0f;
            #pragma unroll
            for (int nt = 0; nt < 8; nt++) {
                __half2 hp0 = h2exp2(__floats2half2_rn(sacc[mt][nt][0] - mn0,
                                                       sacc[mt][nt][1] - mn0));
                __half2 hp1 = h2exp2(__floats2half2_rn(sacc[mt][nt][2] - mn1,
                                                       sacc[mt][nt][3] - mn1));
                *(__half2*)(Ps + rowA * HS2 + nt * 8 + 2 * tq) = hp0;
                *(__half2*)(Ps + (rowA + 8) * HS2 + nt * 8 + 2 * tq) = hp1;
                float2 f0 = __half22float2(hp0);
                float2 f1 = __half22float2(hp1);
                sum0 += f0.x + f0.y;
                sum1 += f1.x + f1.y;
            }
            sum0 += __shfl_xor_sync(0xffffffffu, sum0, 1);
            sum0 += __shfl_xor_sync(0xffffffffu, sum0, 2);
            sum1 += __shfl_xor_sync(0xffffffffu, sum1, 1);
            sum1 += __shfl_xor_sync(0xffffffffu, sum1, 2);

            li[mt][0] = li[mt][0] * al0 + sum0;  mi[mt][0] = mn0;
            li[mt][1] = li[mt][1] * al1 + sum1;  mi[mt][1] = mn1;
            #pragma unroll
            for (int nt = 0; nt < 8; nt++) {
                oacc[mt][nt][0] *= al0; oacc[mt][nt][1] *= al0;
                oacc[mt][nt][2] *= al1; oacc[mt][nt][3] *= al1;
            }
        }
        __syncwarp();   // P rows visible warp-wide before ldmatrix reads

        // ---- O += P V ----
        #pragma unroll
        for (int kc = 0; kc < 4; kc++) {
            uint32_t af[2][4];
            #pragma unroll
            for (int mt = 0; mt < 2; mt++) {
                const int row = w * 32 + mt * 16 + aRowOff;
                const int kh  = kc * 16 + aKOff;
                ldsm4(af[mt], sQu + (uint32_t)(row * HS2 + kh) * 2);
            }
            #pragma unroll
            for (int ntp = 0; ntp < 4; ntp++) {
                uint32_t vf[4];
                const int row = ntp * 16 + bRowOff;
                const int kh  = kc * 16 + bKOff;
                ldsm4(vf, vBase + (uint32_t)(row * HS2 + kh) * 2);
                mma_f16(oacc[0][ntp * 2],     af[0], vf[0], vf[1]);
                mma_f16(oacc[1][ntp * 2],     af[1], vf[0], vf[1]);
                mma_f16(oacc[0][ntp * 2 + 1], af[0], vf[2], vf[3]);
                mma_f16(oacc[1][ntp * 2 + 1], af[1], vf[2], vf[3]);
            }
        }
    }

    // ---- epilogue: fp16 ybuf ----
    #pragma unroll
    for (int mt = 0; mt < 2; mt++) {
        const float inv0 = 1.0f / li[mt][0];
        const float inv1 = 1.0f / li[mt][1];
        const size_t r0 = (size_t)b * TT + q0 + w * 32 + mt * 16 + quad;
        #pragma unroll
        for (int nt = 0; nt < 8; nt++) {
            const int col = h * HD + nt * 8 + 2 * tq;
            *(__half2*)(y + r0 * CC + col) =
                __floats2half2_rn(oacc[mt][nt][0] * inv0, oacc[mt][nt][1] * inv0);
            *(__half2*)(y + (r0 + 8) * CC + col) =
                __floats2half2_rn(oacc[mt][nt][2] * inv1, oacc[mt][nt][3] * inv1);
        }
    }
}

// ---------------------------------------------------------------------------
// Launch
// ---------------------------------------------------------------------------
extern "C" void kernel_launch(void* const* d_in, const int* in_sizes, int n_in,
                              void* d_out, int out_size)
{
    const float* x     = (const float*)d_in[0];
    const float* Wqkv  = (const float*)d_in[1];
    const float* bqkv  = (const float*)d_in[2];
    const float* Wproj = (const float*)d_in[3];
    const float* bproj = (const float*)d_in[4];
    float* out = (float*)d_out;

    float *qkv, *ybuf, *xt, *wt;
    cudaGetSymbolAddress((void**)&qkv, g_qkv);
    cudaGetSymbolAddress((void**)&ybuf, g_y);
    cudaGetSymbolAddress((void**)&xt, g_xt);
    cudaGetSymbolAddress((void**)&wt, g_wt);
    __half* qkvh    = (__half*)qkv;
    __half* vTh     = (__half*)qkv + (size_t)MM * C3;
    __half* xh      = (__half*)xt;
    __half* yh      = (__half*)ybuf;
    __half* wqkvTh  = (__half*)wt;
    __half* wprojTh = (__half*)wt + (size_t)C3 * CC;

    const int smem_gemm = NSTAGE * 2 * TILE_H * sizeof(__half);   // 110592
    cudaFuncSetAttribute((const void*)gemm_f16mma<true, true>,
                         cudaFuncAttributeMaxDynamicSharedMemorySize, smem_gemm);
    cudaFuncSetAttribute((const void*)gemm_f16mma<false, false>,
                         cudaFuncAttributeMaxDynamicSharedMemorySize, smem_gemm);

    const int smem_attn = (128 + 4 * 64) * HS2 * sizeof(__half);  // 55296
    cudaFuncSetAttribute(flash_attn_f16,
                         cudaFuncAttributeMaxDynamicSharedMemorySize, smem_attn);

    // 0) Convert x to fp16; transpose+convert weights to fp16 [N][K].
    {
        int n8 = (MM * CC) / 8;
        conv_f16<<<(n8 + 255) / 256, 256>>>(x, xh, n8);
        transpose_f16<<<dim3(C3 / 32, CC / 32), dim3(32, 8)>>>(Wqkv, wqkvTh, CC, C3);
        transpose_f16<<<dim3(CC / 32, CC / 32), dim3(32, 8)>>>(Wproj, wprojTh, CC, CC);
    }

    // 1) QKV projection (f16 mma; Q/K -> qkvh, V scattered into vTh)
    gemm_f16mma<true, true><<<dim3(C3 / BN, MM / BM), 256, smem_gemm>>>(
        xh, wqkvTh, bqkv, qkvh, vTh, MM, C3, CC);

    // 2) Causal flash attention (f16 mma + ldmatrix, f16x2 exp) -> fp16 ybuf
    flash_attn_f16<<<dim3(TT / BQ, HH, BB), 128, smem_attn>>>(qkvh, vTh, yh);

    // 3) Output projection (f16 mma; fp32 out)
    gemm_f16mma<false, false><<<dim3(CC / BN, MM / BM), 256, smem_gemm>>>(
        yh, wprojTh, bproj, out, nullptr, MM, CC, CC);
}